// round 11
// baseline (speedup 1.0000x reference)
#include <cuda_runtime.h>
#include <cstdint>
#include <math.h>

#define B_    2
#define N_    65536
#define HID_  64
#define C_    128
#define NPB   32      // points per block (k_zr)
#define NPQ   64      // points per block (k_q)
#define AP    132     // aggT row pad in floats

typedef unsigned int u32;

// Scratch (static device globals)
__device__ float  g_hx[(size_t)B_ * N_ * C_];    // [b][n][c] c<64: h, c>=64: x
__device__ float  g_rh[(size_t)B_ * N_ * HID_];  // [b][n][o] r*h
__device__ float  g_z [(size_t)B_ * N_ * HID_];  // [b][n][o] sigmoid(z)
__device__ float4 g_wF[3 * 4 * 16 * 32];         // [gate][mt][kt][lane] A-fragments (tf32)
__device__ float4 g_wp4[3 * C_];                 // [g][c] = (w0,w1,w2,bias)

__device__ __forceinline__ float sigm(float v) { return 1.0f / (1.0f + __expf(-v)); }

__device__ __forceinline__ float tf32r(float v) {
    u32 r; asm("cvt.rna.tf32.f32 %0, %1;" : "=r"(r) : "f"(v));
    return __uint_as_float(r);
}

__device__ __forceinline__ void mma_tf32(float4& d, u32 a0, u32 a1, u32 a2, u32 a3,
                                         u32 b0, u32 b1) {
    asm volatile(
        "mma.sync.aligned.m16n8k8.row.col.f32.tf32.tf32.f32 "
        "{%0,%1,%2,%3}, {%4,%5,%6,%7}, {%8,%9}, {%0,%1,%2,%3};"
        : "+f"(d.x), "+f"(d.y), "+f"(d.z), "+f"(d.w)
        : "r"(a0), "r"(a1), "r"(a2), "r"(a3), "r"(b0), "r"(b1));
}

// ---------------------------------------------------------------------------
// Weight prep: A-fragments (tf32) for mma + packed position weights
// ---------------------------------------------------------------------------
__global__ void k_wT(const float* __restrict__ wz, const float* __restrict__ wr,
                     const float* __restrict__ wq,
                     const float* __restrict__ wzp, const float* __restrict__ bzp,
                     const float* __restrict__ wrp, const float* __restrict__ brp,
                     const float* __restrict__ wqp, const float* __restrict__ bqp) {
    int i = blockIdx.x * blockDim.x + threadIdx.x;
    if (i < 3 * 4 * 16 * 32) {
        int gate = i >> 11;
        int r    = i & 2047;
        int mt   = r >> 9;
        int r2   = r & 511;
        int kt   = r2 >> 5;
        int lane = r2 & 31;
        int g = lane >> 2, t = lane & 3;
        int o = 16 * mt + g, c = 8 * kt + t;
        const float* w = (gate == 0) ? wz : ((gate == 1) ? wr : wq);
        float4 f;
        f.x = tf32r(w[o * C_ + c]);
        f.y = tf32r(w[(o + 8) * C_ + c]);
        f.z = tf32r(w[o * C_ + c + 4]);
        f.w = tf32r(w[(o + 8) * C_ + c + 4]);
        g_wF[i] = f;
    }
    if (i < 3 * C_) {
        int g = i >> 7, c = i & 127;
        const float* wp = (g == 0) ? wzp : ((g == 1) ? wrp : wqp);
        const float* bp = (g == 0) ? bzp : ((g == 1) ? brp : bqp);
        g_wp4[i] = make_float4(wp[3 * c], wp[3 * c + 1], wp[3 * c + 2], bp[c]);
    }
}

// ---------------------------------------------------------------------------
// Transpose: g_hx[b][n][c] = (c<64 ? h[b][c][n] : x[b][c-64][n])  64-pt tiles
// ---------------------------------------------------------------------------
__global__ __launch_bounds__(256) void k_tr(const float* __restrict__ h,
                                            const float* __restrict__ x) {
    __shared__ float t[C_][66];
    const int b  = blockIdx.x >> 10;
    const int n0 = (blockIdx.x & 1023) * 64;
    const int tid  = threadIdx.x;
    const int lane = tid & 31;
    const int w    = tid >> 5;

    for (int r = w; r < C_; r += 8) {
        const float* src = (r < HID_)
            ? (h + ((size_t)(b * HID_ + r)) * N_)
            : (x + ((size_t)(b * HID_ + (r - HID_))) * N_);
        t[r][lane]      = src[n0 + lane];
        t[r][lane + 32] = src[n0 + lane + 32];
    }
    __syncthreads();

    const int nn = tid >> 2;
    const int q0 = tid & 3;
    float* dst = g_hx + ((size_t)(b * N_ + n0 + nn)) * C_;
#pragma unroll
    for (int k = 0; k < 8; k++) {
        int c = 4 * (q0 + 4 * k);
        float4 v = make_float4(t[c][nn], t[c + 1][nn], t[c + 2][nn], t[c + 3][nn]);
        *(float4*)(dst + c) = v;
    }
}

// ---------------------------------------------------------------------------
// ZR kernel: 32 points/block, 256 threads. zsm/rsm alias aggT storage.
// ---------------------------------------------------------------------------
__global__ __launch_bounds__(256, 5) void k_zr(
    const float* __restrict__ xyz, const int* __restrict__ knn,
    const float* __restrict__ bzo, const float* __restrict__ bro) {
    __shared__ __align__(16) float sbuf[2 * NPB * AP];
    __shared__ float4 srel4[NPB][4];
    __shared__ int    sidx[NPB][4];

    float (*aggT)[NPB][AP] = (float(*)[NPB][AP])sbuf;
    float (*zsm)[65] = (float(*)[65])sbuf;
    float (*rsm)[65] = (float(*)[65])(sbuf + NPB * 65);

    const int b   = blockIdx.x >> 11;
    const int n0  = (blockIdx.x & 2047) * NPB;
    const int tid = threadIdx.x;
    const int lane = tid & 31;
    const int w    = tid >> 5;

    if (tid < NPB * 4) {
        int pt = tid >> 2, j = tid & 3;
        int n  = n0 + pt;
        int m  = knn[((size_t)b * N_ + n) * 4 + j];
        sidx[pt][j] = m;
        const float* xb = xyz + (size_t)b * 3 * N_;
        srel4[pt][j] = make_float4(xb[m] - xb[n],
                                   xb[N_ + m] - xb[N_ + n],
                                   xb[2 * N_ + m] - xb[2 * N_ + n], 0.f);
    }
    __syncthreads();

    // Phase 1: gather + shared moments -> both gates' depthwise agg
    {
        const int half = w & 1;
        const int ptb  = w >> 1;
        const int c0   = half * HID_ + 2 * lane;
        const float4 Wz0 = g_wp4[c0],      Wz1 = g_wp4[c0 + 1];
        const float4 Wr0 = g_wp4[C_ + c0], Wr1 = g_wp4[C_ + c0 + 1];
        const float* hxb = g_hx + (size_t)b * N_ * C_ + c0;
#pragma unroll
        for (int u = 0; u < 8; u++) {
            const int pt = ptb + 4 * u;
            int m[4];
#pragma unroll
            for (int j = 0; j < 4; j++) m[j] = sidx[pt][j];
            float2 gv[4];
#pragma unroll
            for (int j = 0; j < 4; j++)
                gv[j] = *(const float2*)(hxb + (size_t)m[j] * C_);

            float m0a = 0.f, m1a = 0.f, m2a = 0.f, m3a = 0.f;
            float m0b = 0.f, m1b = 0.f, m2b = 0.f, m3b = 0.f;
#pragma unroll
            for (int j = 0; j < 4; j++) {
                float4 R = srel4[pt][j];
                float ga = gv[j].x, gb = gv[j].y;
                m0a += ga; m1a = fmaf(R.x, ga, m1a);
                m2a = fmaf(R.y, ga, m2a); m3a = fmaf(R.z, ga, m3a);
                m0b += gb; m1b = fmaf(R.x, gb, m1b);
                m2b = fmaf(R.y, gb, m2b); m3b = fmaf(R.z, gb, m3b);
            }
            float az0 = fmaf(Wz0.x, m1a, fmaf(Wz0.y, m2a, fmaf(Wz0.z, m3a, Wz0.w * m0a)));
            float az1 = fmaf(Wz1.x, m1b, fmaf(Wz1.y, m2b, fmaf(Wz1.z, m3b, Wz1.w * m0b)));
            float ar0 = fmaf(Wr0.x, m1a, fmaf(Wr0.y, m2a, fmaf(Wr0.z, m3a, Wr0.w * m0a)));
            float ar1 = fmaf(Wr1.x, m1b, fmaf(Wr1.y, m2b, fmaf(Wr1.z, m3b, Wr1.w * m0b)));
            *(float2*)&aggT[0][pt][c0] = make_float2(tf32r(az0), tf32r(az1));
            *(float2*)&aggT[1][pt][c0] = make_float2(tf32r(ar0), tf32r(ar1));
        }
    }
    __syncthreads();

    // Phase 2: tf32 mma. warp = (gate g2, m-tile mt); 4 n-tiles x 16 k-tiles
    {
        const int g2 = w >> 2;
        const int mt = w & 3;
        const int g  = lane >> 2, t = lane & 3;
        const float4* wf = g_wF + ((size_t)(g2 * 4 + mt) * 16) * 32 + lane;

        float4 acc[4];
#pragma unroll
        for (int nt = 0; nt < 4; nt++) acc[nt] = make_float4(0.f, 0.f, 0.f, 0.f);

#pragma unroll 4
        for (int kt = 0; kt < 16; kt++) {
            float4 A = wf[kt * 32];
            u32 a0 = __float_as_uint(A.x), a1 = __float_as_uint(A.y);
            u32 a2 = __float_as_uint(A.z), a3 = __float_as_uint(A.w);
#pragma unroll
            for (int nt = 0; nt < 4; nt++) {
                u32 b0 = __float_as_uint(aggT[g2][8 * nt + g][8 * kt + t]);
                u32 b1 = __float_as_uint(aggT[g2][8 * nt + g][8 * kt + t + 4]);
                mma_tf32(acc[nt], a0, a1, a2, a3, b0, b1);
            }
        }
        __syncthreads();

        const float* bo = g2 ? bro : bzo;
        const float b0v = bo[16 * mt + g];
        const float b1v = bo[16 * mt + g + 8];
        float (*dst)[65] = g2 ? rsm : zsm;
#pragma unroll
        for (int nt = 0; nt < 4; nt++) {
            int pt = 8 * nt + 2 * t;
            int o  = 16 * mt + g;
            dst[pt][o]         = sigm(acc[nt].x + b0v);
            dst[pt + 1][o]     = sigm(acc[nt].y + b0v);
            dst[pt][o + 8]     = sigm(acc[nt].z + b1v);
            dst[pt + 1][o + 8] = sigm(acc[nt].w + b1v);
        }
    }
    __syncthreads();

    // Phase 3: coalesced writes
    for (int i = tid; i < NPB * HID_; i += 256) {
        int pt = i >> 6, o = i & 63;
        size_t nb = (size_t)(b * N_ + n0 + pt);
        g_z[nb * HID_ + o] = zsm[pt][o];
        float hv = g_hx[nb * C_ + o];
        g_rh[nb * HID_ + o] = rsm[pt][o] * hv;
    }
}

// ---------------------------------------------------------------------------
// Q kernel: 64 points/block, 256 threads. Full-row float4 gathers (warp=pt).
// osm aliases aggT storage.
// ---------------------------------------------------------------------------
__global__ __launch_bounds__(256, 4) void k_q(
    const float* __restrict__ xyz, const int* __restrict__ knn,
    const float* __restrict__ bqo, float* __restrict__ out) {
    __shared__ __align__(16) float sbuf[NPQ * AP];
    __shared__ float4 srel4[NPQ][4];
    __shared__ int    sidx[NPQ][4];

    float (*aggT)[AP] = (float(*)[AP])sbuf;
    float (*osm)[65]  = (float(*)[65])sbuf;   // alias (post-sync)

    const int b   = blockIdx.x >> 10;
    const int n0  = (blockIdx.x & 1023) * NPQ;
    const int tid = threadIdx.x;
    const int lane = tid & 31;
    const int w    = tid >> 5;

    if (tid < NPQ * 4) {
        int pt = tid >> 2, j = tid & 3;
        int n  = n0 + pt;
        int m  = knn[((size_t)b * N_ + n) * 4 + j];
        sidx[pt][j] = m;
        const float* xb = xyz + (size_t)b * 3 * N_;
        srel4[pt][j] = make_float4(xb[m] - xb[n],
                                   xb[N_ + m] - xb[N_ + n],
                                   xb[2 * N_ + m] - xb[2 * N_ + n], 0.f);
    }
    __syncthreads();

    // Phase 1: full-row gather (warp=pt; lanes 0-15: r*h, 16-31: x half)
    {
        const int  c4   = 4 * lane;
        const bool isrh = (lane < 16);
        const float* gb = isrh
            ? (g_rh + (size_t)b * N_ * HID_ + c4)
            : (g_hx + (size_t)b * N_ * C_ + HID_ + (c4 - 64));
        const int stride = isrh ? HID_ : C_;
        float4 Wq[4];
#pragma unroll
        for (int ch = 0; ch < 4; ch++) Wq[ch] = g_wp4[2 * C_ + c4 + ch];

#pragma unroll
        for (int u = 0; u < 8; u++) {
            const int pt = w + 8 * u;
            float4 gv[4];
#pragma unroll
            for (int j = 0; j < 4; j++)
                gv[j] = *(const float4*)(gb + (size_t)sidx[pt][j] * stride);

            float m0[4], m1[4], m2[4], m3[4];
#pragma unroll
            for (int ch = 0; ch < 4; ch++) { m0[ch] = m1[ch] = m2[ch] = m3[ch] = 0.f; }
#pragma unroll
            for (int j = 0; j < 4; j++) {
                float4 R = srel4[pt][j];
                float gc[4] = {gv[j].x, gv[j].y, gv[j].z, gv[j].w};
#pragma unroll
                for (int ch = 0; ch < 4; ch++) {
                    m0[ch] += gc[ch];
                    m1[ch] = fmaf(R.x, gc[ch], m1[ch]);
                    m2[ch] = fmaf(R.y, gc[ch], m2[ch]);
                    m3[ch] = fmaf(R.z, gc[ch], m3[ch]);
                }
            }
            float4 a;
            a.x = tf32r(fmaf(Wq[0].x, m1[0], fmaf(Wq[0].y, m2[0], fmaf(Wq[0].z, m3[0], Wq[0].w * m0[0]))));
            a.y = tf32r(fmaf(Wq[1].x, m1[1], fmaf(Wq[1].y, m2[1], fmaf(Wq[1].z, m3[1], Wq[1].w * m0[1]))));
            a.z = tf32r(fmaf(Wq[2].x, m1[2], fmaf(Wq[2].y, m2[2], fmaf(Wq[2].z, m3[2], Wq[2].w * m0[2]))));
            a.w = tf32r(fmaf(Wq[3].x, m1[3], fmaf(Wq[3].y, m2[3], fmaf(Wq[3].z, m3[3], Wq[3].w * m0[3]))));
            *(float4*)&aggT[pt][c4] = a;
        }
    }
    __syncthreads();

    // Phase 2: tf32 mma. warp = (m-tile mt, n-quarter nh); 4 nt x 16 kt
    {
        const int mt = w & 3;
        const int nh = w >> 2;            // 0..1 -> n-tiles {4nh..4nh+3}
        const int g  = lane >> 2, t = lane & 3;
        const float4* wf = g_wF + ((size_t)(2 * 4 + mt) * 16) * 32 + lane;

        float4 acc[4];
#pragma unroll
        for (int j = 0; j < 4; j++) acc[j] = make_float4(0.f, 0.f, 0.f, 0.f);

#pragma unroll 4
        for (int kt = 0; kt < 16; kt++) {
            float4 A = wf[kt * 32];
            u32 a0 = __float_as_uint(A.x), a1 = __float_as_uint(A.y);
            u32 a2 = __float_as_uint(A.z), a3 = __float_as_uint(A.w);
#pragma unroll
            for (int j = 0; j < 4; j++) {
                int nt = 4 * nh + j;
                u32 b0 = __float_as_uint(aggT[8 * nt + g][8 * kt + t]);
                u32 b1 = __float_as_uint(aggT[8 * nt + g][8 * kt + t + 4]);
                mma_tf32(acc[j], a0, a1, a2, a3, b0, b1);
            }
        }
        __syncthreads();   // aggT dead; osm may now overwrite it

        const float b0v = bqo[16 * mt + g];
        const float b1v = bqo[16 * mt + g + 8];
#pragma unroll
        for (int j = 0; j < 4; j++) {
            int pt = 8 * (4 * nh + j) + 2 * t;
            int o  = 16 * mt + g;
            osm[pt][o]         = tanhf(acc[j].x + b0v);
            osm[pt + 1][o]     = tanhf(acc[j].y + b0v);
            osm[pt][o + 8]     = tanhf(acc[j].z + b1v);
            osm[pt + 1][o + 8] = tanhf(acc[j].w + b1v);
        }
    }
    __syncthreads();

    // GRU combine (coalesced loads), update osm in place
    for (int i = tid; i < NPQ * HID_; i += 256) {
        int pt = i >> 6, o = i & 63;
        size_t nb = (size_t)(b * N_ + n0 + pt);
        float z  = g_z [nb * HID_ + o];
        float hv = g_hx[nb * C_ + o];
        float qv = osm[pt][o];
        osm[pt][o] = fmaf(z, qv - hv, hv);
    }
    __syncthreads();

    // Phase 3: coalesced transposed output out[b][o][n0..n0+63]
    {
        const int o = tid >> 2;
        const int q = tid & 3;
#pragma unroll
        for (int rep = 0; rep < 4; rep++) {
            int nb = 16 * q + 4 * rep;
            float4 v = make_float4(osm[nb][o], osm[nb + 1][o],
                                   osm[nb + 2][o], osm[nb + 3][o]);
            *(float4*)(out + ((size_t)(b * HID_ + o)) * N_ + n0 + nb) = v;
        }
    }
}

// ---------------------------------------------------------------------------
extern "C" void kernel_launch(void* const* d_in, const int* in_sizes, int n_in,
                              void* d_out, int out_size) {
    const float* xyz = (const float*)d_in[0];
    const float* h   = (const float*)d_in[1];
    const float* x   = (const float*)d_in[2];
    const int*   knn = (const int*)  d_in[3];
    const float* wzp = (const float*)d_in[4];
    const float* bzp = (const float*)d_in[5];
    const float* wzo = (const float*)d_in[6];
    const float* bzo = (const float*)d_in[7];
    const float* wrp = (const float*)d_in[8];
    const float* brp = (const float*)d_in[9];
    const float* wro = (const float*)d_in[10];
    const float* bro = (const float*)d_in[11];
    const float* wqp = (const float*)d_in[12];
    const float* bqp = (const float*)d_in[13];
    const float* wqo = (const float*)d_in[14];
    const float* bqo = (const float*)d_in[15];
    float* out = (float*)d_out;

    k_wT<<<24, 256>>>(wzo, wro, wqo, wzp, bzp, wrp, brp, wqp, bqp);
    k_tr<<<(B_ * N_) / 64, 256>>>(h, x);
    k_zr<<<(B_ * N_) / NPB, 256>>>(xyz, knn, bzo, bro);
    k_q <<<(B_ * N_) / NPQ, 256>>>(xyz, knn, bqo, out);
}

// round 12
// speedup vs baseline: 1.1976x; 1.1976x over previous
#include <cuda_runtime.h>
#include <cuda_fp16.h>
#include <cstdint>
#include <math.h>

#define B_    2
#define N_    65536
#define HID_  64
#define C_    128
#define NPB   32      // points per block (k_zr / k_q)
#define AP    132     // aggT row pad in floats

typedef unsigned int u32;

// Scratch (static device globals)
__device__ __half g_hx[(size_t)B_ * N_ * C_];    // [b][n][c] c<64: h, c>=64: x (fp16)
__device__ __half g_rh[(size_t)B_ * N_ * HID_];  // [b][n][o] r*h (fp16)
__device__ float  g_z [(size_t)B_ * HID_ * N_];  // [b][o][n] sigmoid(z)  (TRANSPOSED)
__device__ float4 g_wF[3 * 4 * 16 * 32];         // [gate][mt][kt][lane] A-fragments (tf32)
__device__ float4 g_wp4[3 * C_];                 // [g][c] = (w0,w1,w2,bias)

__device__ __forceinline__ float sigm(float v) { return 1.0f / (1.0f + __expf(-v)); }

__device__ __forceinline__ float tf32r(float v) {
    u32 r; asm("cvt.rna.tf32.f32 %0, %1;" : "=r"(r) : "f"(v));
    return __uint_as_float(r);
}

__device__ __forceinline__ void mma_tf32(float4& d, u32 a0, u32 a1, u32 a2, u32 a3,
                                         u32 b0, u32 b1) {
    asm volatile(
        "mma.sync.aligned.m16n8k8.row.col.f32.tf32.tf32.f32 "
        "{%0,%1,%2,%3}, {%4,%5,%6,%7}, {%8,%9}, {%0,%1,%2,%3};"
        : "+f"(d.x), "+f"(d.y), "+f"(d.z), "+f"(d.w)
        : "r"(a0), "r"(a1), "r"(a2), "r"(a3), "r"(b0), "r"(b1));
}

// ---------------------------------------------------------------------------
// Weight prep: A-fragments (tf32) for mma + packed position weights
// ---------------------------------------------------------------------------
__global__ void k_wT(const float* __restrict__ wz, const float* __restrict__ wr,
                     const float* __restrict__ wq,
                     const float* __restrict__ wzp, const float* __restrict__ bzp,
                     const float* __restrict__ wrp, const float* __restrict__ brp,
                     const float* __restrict__ wqp, const float* __restrict__ bqp) {
    int i = blockIdx.x * blockDim.x + threadIdx.x;
    if (i < 3 * 4 * 16 * 32) {
        int gate = i >> 11;
        int r    = i & 2047;
        int mt   = r >> 9;
        int r2   = r & 511;
        int kt   = r2 >> 5;
        int lane = r2 & 31;
        int g = lane >> 2, t = lane & 3;
        int o = 16 * mt + g, c = 8 * kt + t;
        const float* w = (gate == 0) ? wz : ((gate == 1) ? wr : wq);
        float4 f;
        f.x = tf32r(w[o * C_ + c]);
        f.y = tf32r(w[(o + 8) * C_ + c]);
        f.z = tf32r(w[o * C_ + c + 4]);
        f.w = tf32r(w[(o + 8) * C_ + c + 4]);
        g_wF[i] = f;
    }
    if (i < 3 * C_) {
        int g = i >> 7, c = i & 127;
        const float* wp = (g == 0) ? wzp : ((g == 1) ? wrp : wqp);
        const float* bp = (g == 0) ? bzp : ((g == 1) ? brp : bqp);
        g_wp4[i] = make_float4(wp[3 * c], wp[3 * c + 1], wp[3 * c + 2], bp[c]);
    }
}

// ---------------------------------------------------------------------------
// Transpose: g_hx[b][n][c] = fp16(c<64 ? h[b][c][n] : x[b][c-64][n])  64-pt tiles
// ---------------------------------------------------------------------------
__global__ __launch_bounds__(256) void k_tr(const float* __restrict__ h,
                                            const float* __restrict__ x) {
    __shared__ float t[C_][66];
    const int b  = blockIdx.x >> 10;
    const int n0 = (blockIdx.x & 1023) * 64;
    const int tid  = threadIdx.x;
    const int lane = tid & 31;
    const int w    = tid >> 5;

    for (int r = w; r < C_; r += 8) {
        const float* src = (r < HID_)
            ? (h + ((size_t)(b * HID_ + r)) * N_)
            : (x + ((size_t)(b * HID_ + (r - HID_))) * N_);
        t[r][lane]      = src[n0 + lane];
        t[r][lane + 32] = src[n0 + lane + 32];
    }
    __syncthreads();

    const int nn = tid >> 2;          // 64 points, 4 threads per point
    const int q0 = tid & 3;
    __half* dst = g_hx + ((size_t)(b * N_ + n0 + nn)) * C_;
#pragma unroll
    for (int k = 0; k < 8; k++) {
        int c = 4 * (q0 + 4 * k);
        __half2 lo = __floats2half2_rn(t[c][nn],     t[c + 1][nn]);
        __half2 hi = __floats2half2_rn(t[c + 2][nn], t[c + 3][nn]);
        uint2 pk = make_uint2(*(u32*)&lo, *(u32*)&hi);
        *(uint2*)(dst + c) = pk;
    }
}

// ---------------------------------------------------------------------------
// ZR kernel: 32 points/block, 256 threads. fp16 gathers; zsm/rsm alias aggT.
// ---------------------------------------------------------------------------
__global__ __launch_bounds__(256, 5) void k_zr(
    const float* __restrict__ xyz, const int* __restrict__ knn,
    const float* __restrict__ bzo, const float* __restrict__ bro) {
    __shared__ __align__(16) float sbuf[2 * NPB * AP];
    __shared__ float4 srel4[NPB][4];
    __shared__ int    sidx[NPB][4];

    float (*aggT)[NPB][AP] = (float(*)[NPB][AP])sbuf;
    float (*zsm)[65] = (float(*)[65])sbuf;               // alias (post-sync)
    float (*rsm)[65] = (float(*)[65])(sbuf + NPB * 65);

    const int b   = blockIdx.x >> 11;
    const int n0  = (blockIdx.x & 2047) * NPB;
    const int tid = threadIdx.x;
    const int lane = tid & 31;
    const int w    = tid >> 5;

    if (tid < NPB * 4) {
        int pt = tid >> 2, j = tid & 3;
        int n  = n0 + pt;
        int m  = knn[((size_t)b * N_ + n) * 4 + j];
        sidx[pt][j] = m;
        const float* xb = xyz + (size_t)b * 3 * N_;
        srel4[pt][j] = make_float4(xb[m] - xb[n],
                                   xb[N_ + m] - xb[N_ + n],
                                   xb[2 * N_ + m] - xb[2 * N_ + n], 0.f);
    }
    __syncthreads();

    // Phase 1: fp16 gather + shared moments -> both gates' depthwise agg
    {
        const int half = w & 1;
        const int ptb  = w >> 1;
        const int c0   = half * HID_ + 2 * lane;
        const float4 Wz0 = g_wp4[c0],      Wz1 = g_wp4[c0 + 1];
        const float4 Wr0 = g_wp4[C_ + c0], Wr1 = g_wp4[C_ + c0 + 1];
        const __half* hxb = g_hx + (size_t)b * N_ * C_ + c0;
#pragma unroll
        for (int u = 0; u < 8; u++) {
            const int pt = ptb + 4 * u;
            int m[4];
#pragma unroll
            for (int j = 0; j < 4; j++) m[j] = sidx[pt][j];
            float2 gv[4];
#pragma unroll
            for (int j = 0; j < 4; j++)
                gv[j] = __half22float2(*(const __half2*)(hxb + (size_t)m[j] * C_));

            float m0a = 0.f, m1a = 0.f, m2a = 0.f, m3a = 0.f;
            float m0b = 0.f, m1b = 0.f, m2b = 0.f, m3b = 0.f;
#pragma unroll
            for (int j = 0; j < 4; j++) {
                float4 R = srel4[pt][j];
                float ga = gv[j].x, gb = gv[j].y;
                m0a += ga; m1a = fmaf(R.x, ga, m1a);
                m2a = fmaf(R.y, ga, m2a); m3a = fmaf(R.z, ga, m3a);
                m0b += gb; m1b = fmaf(R.x, gb, m1b);
                m2b = fmaf(R.y, gb, m2b); m3b = fmaf(R.z, gb, m3b);
            }
            float az0 = fmaf(Wz0.x, m1a, fmaf(Wz0.y, m2a, fmaf(Wz0.z, m3a, Wz0.w * m0a)));
            float az1 = fmaf(Wz1.x, m1b, fmaf(Wz1.y, m2b, fmaf(Wz1.z, m3b, Wz1.w * m0b)));
            float ar0 = fmaf(Wr0.x, m1a, fmaf(Wr0.y, m2a, fmaf(Wr0.z, m3a, Wr0.w * m0a)));
            float ar1 = fmaf(Wr1.x, m1b, fmaf(Wr1.y, m2b, fmaf(Wr1.z, m3b, Wr1.w * m0b)));
            *(float2*)&aggT[0][pt][c0] = make_float2(tf32r(az0), tf32r(az1));
            *(float2*)&aggT[1][pt][c0] = make_float2(tf32r(ar0), tf32r(ar1));
        }
    }
    __syncthreads();

    // Phase 2: tf32 mma. warp = (gate g2, m-tile mt); 4 n-tiles x 16 k-tiles
    {
        const int g2 = w >> 2;
        const int mt = w & 3;
        const int g  = lane >> 2, t = lane & 3;
        const float4* wf = g_wF + ((size_t)(g2 * 4 + mt) * 16) * 32 + lane;

        float4 acc[4];
#pragma unroll
        for (int nt = 0; nt < 4; nt++) acc[nt] = make_float4(0.f, 0.f, 0.f, 0.f);

#pragma unroll 4
        for (int kt = 0; kt < 16; kt++) {
            float4 A = wf[kt * 32];
            u32 a0 = __float_as_uint(A.x), a1 = __float_as_uint(A.y);
            u32 a2 = __float_as_uint(A.z), a3 = __float_as_uint(A.w);
#pragma unroll
            for (int nt = 0; nt < 4; nt++) {
                u32 b0 = __float_as_uint(aggT[g2][8 * nt + g][8 * kt + t]);
                u32 b1 = __float_as_uint(aggT[g2][8 * nt + g][8 * kt + t + 4]);
                mma_tf32(acc[nt], a0, a1, a2, a3, b0, b1);
            }
        }
        __syncthreads();   // aggT dead; zsm/rsm may now overwrite it

        const float* bo = g2 ? bro : bzo;
        const float b0v = bo[16 * mt + g];
        const float b1v = bo[16 * mt + g + 8];
        float (*dst)[65] = g2 ? rsm : zsm;
#pragma unroll
        for (int nt = 0; nt < 4; nt++) {
            int pt = 8 * nt + 2 * t;
            int o  = 16 * mt + g;
            dst[pt][o]         = sigm(acc[nt].x + b0v);
            dst[pt + 1][o]     = sigm(acc[nt].y + b0v);
            dst[pt][o + 8]     = sigm(acc[nt].z + b1v);
            dst[pt + 1][o + 8] = sigm(acc[nt].w + b1v);
        }
    }
    __syncthreads();

    // Phase 3a: z -> g_z transposed [b][o][n], coalesced float4 (conflict-free LDS)
    {
        const int o = tid >> 2;
        const int q = tid & 3;
#pragma unroll
        for (int rep = 0; rep < 2; rep++) {
            int nb = 8 * q + 4 * rep;
            float4 v = make_float4(zsm[nb][o], zsm[nb + 1][o],
                                   zsm[nb + 2][o], zsm[nb + 3][o]);
            *(float4*)(g_z + ((size_t)(b * HID_ + o)) * N_ + n0 + nb) = v;
        }
    }
    // Phase 3b: r*h -> g_rh fp16 (half2 per thread)
    for (int i = tid; i < NPB * 32; i += 256) {
        int pt = i >> 5, o2 = 2 * (i & 31);
        size_t nb = (size_t)(b * N_ + n0 + pt);
        float2 hv = __half22float2(*(const __half2*)(g_hx + nb * C_ + o2));
        __half2 rh = __floats2half2_rn(rsm[pt][o2] * hv.x, rsm[pt][o2 + 1] * hv.y);
        *(__half2*)(g_rh + nb * HID_ + o2) = rh;
    }
}

// ---------------------------------------------------------------------------
// Q kernel: 32 points/block, 256 threads. fp16 gathers; osm aliases aggT.
// GRU combine fused into output phase with fp32 h from the ORIGINAL input.
// ---------------------------------------------------------------------------
__global__ __launch_bounds__(256, 6) void k_q(
    const float* __restrict__ xyz, const int* __restrict__ knn,
    const float* __restrict__ bqo, const float* __restrict__ hin,
    float* __restrict__ out) {
    __shared__ __align__(16) float sbuf[NPB * AP];
    __shared__ float4 srel4[NPB][4];
    __shared__ int    sidx[NPB][4];

    float (*aggT)[AP] = (float(*)[AP])sbuf;
    float (*osm)[65]  = (float(*)[65])sbuf;   // alias (post-sync)

    const int b   = blockIdx.x >> 11;
    const int n0  = (blockIdx.x & 2047) * NPB;
    const int tid = threadIdx.x;
    const int lane = tid & 31;
    const int w    = tid >> 5;

    if (tid < NPB * 4) {
        int pt = tid >> 2, j = tid & 3;
        int n  = n0 + pt;
        int m  = knn[((size_t)b * N_ + n) * 4 + j];
        sidx[pt][j] = m;
        const float* xb = xyz + (size_t)b * 3 * N_;
        srel4[pt][j] = make_float4(xb[m] - xb[n],
                                   xb[N_ + m] - xb[N_ + n],
                                   xb[2 * N_ + m] - xb[2 * N_ + n], 0.f);
    }
    __syncthreads();

    // Phase 1: fp16 gather r*h (half 0) or x (half 1) + depthwise agg
    {
        const int half = w & 1;
        const int ptb  = w >> 1;
        const int c0   = half * HID_ + 2 * lane;
        const float4 W0 = g_wp4[2 * C_ + c0], W1 = g_wp4[2 * C_ + c0 + 1];
        const __half* gbase = half
            ? (g_hx + (size_t)b * N_ * C_ + HID_ + 2 * lane)
            : (g_rh + (size_t)b * N_ * HID_ + 2 * lane);
        const int stride = half ? C_ : HID_;
#pragma unroll
        for (int u = 0; u < 8; u++) {
            const int pt = ptb + 4 * u;
            int m[4];
#pragma unroll
            for (int j = 0; j < 4; j++) m[j] = sidx[pt][j];
            float2 gv[4];
#pragma unroll
            for (int j = 0; j < 4; j++)
                gv[j] = __half22float2(*(const __half2*)(gbase + (size_t)m[j] * stride));

            float m0a = 0.f, m1a = 0.f, m2a = 0.f, m3a = 0.f;
            float m0b = 0.f, m1b = 0.f, m2b = 0.f, m3b = 0.f;
#pragma unroll
            for (int j = 0; j < 4; j++) {
                float4 R = srel4[pt][j];
                float ga = gv[j].x, gb = gv[j].y;
                m0a += ga; m1a = fmaf(R.x, ga, m1a);
                m2a = fmaf(R.y, ga, m2a); m3a = fmaf(R.z, ga, m3a);
                m0b += gb; m1b = fmaf(R.x, gb, m1b);
                m2b = fmaf(R.y, gb, m2b); m3b = fmaf(R.z, gb, m3b);
            }
            float a0 = fmaf(W0.x, m1a, fmaf(W0.y, m2a, fmaf(W0.z, m3a, W0.w * m0a)));
            float a1 = fmaf(W1.x, m1b, fmaf(W1.y, m2b, fmaf(W1.z, m3b, W1.w * m0b)));
            *(float2*)&aggT[pt][c0] = make_float2(tf32r(a0), tf32r(a1));
        }
    }
    __syncthreads();

    // Phase 2: tf32 mma. warp = (m-tile mt, n-half nh); tanh -> osm (aliased)
    {
        const int mt = w & 3;
        const int nh = w >> 2;
        const int g  = lane >> 2, t = lane & 3;
        const float4* wf = g_wF + ((size_t)(2 * 4 + mt) * 16) * 32 + lane;

        float4 acc[2];
        acc[0] = make_float4(0.f, 0.f, 0.f, 0.f);
        acc[1] = make_float4(0.f, 0.f, 0.f, 0.f);

#pragma unroll 4
        for (int kt = 0; kt < 16; kt++) {
            float4 A = wf[kt * 32];
            u32 a0 = __float_as_uint(A.x), a1 = __float_as_uint(A.y);
            u32 a2 = __float_as_uint(A.z), a3 = __float_as_uint(A.w);
#pragma unroll
            for (int j = 0; j < 2; j++) {
                int nt = 2 * nh + j;
                u32 b0 = __float_as_uint(aggT[8 * nt + g][8 * kt + t]);
                u32 b1 = __float_as_uint(aggT[8 * nt + g][8 * kt + t + 4]);
                mma_tf32(acc[j], a0, a1, a2, a3, b0, b1);
            }
        }
        __syncthreads();   // aggT dead; osm may now overwrite it

        const float b0v = bqo[16 * mt + g];
        const float b1v = bqo[16 * mt + g + 8];
#pragma unroll
        for (int j = 0; j < 2; j++) {
            int pt = 8 * (2 * nh + j) + 2 * t;
            int o  = 16 * mt + g;
            osm[pt][o]         = tanhf(acc[j].x + b0v);
            osm[pt + 1][o]     = tanhf(acc[j].y + b0v);
            osm[pt][o + 8]     = tanhf(acc[j].z + b1v);
            osm[pt + 1][o + 8] = tanhf(acc[j].w + b1v);
        }
    }
    __syncthreads();

    // Phase 3: fused GRU combine + coalesced output. z/h/out all [b][o][n].
    {
        const int o = tid >> 2;
        const int q = tid & 3;
        size_t rowbase = ((size_t)(b * HID_ + o)) * N_ + n0;
#pragma unroll
        for (int rep = 0; rep < 2; rep++) {
            int nb = 8 * q + 4 * rep;
            float4 zv = *(const float4*)(g_z + rowbase + nb);
            float4 hv = *(const float4*)(hin + rowbase + nb);
            float4 v;
            v.x = fmaf(zv.x, osm[nb][o]     - hv.x, hv.x);
            v.y = fmaf(zv.y, osm[nb + 1][o] - hv.y, hv.y);
            v.z = fmaf(zv.z, osm[nb + 2][o] - hv.z, hv.z);
            v.w = fmaf(zv.w, osm[nb + 3][o] - hv.w, hv.w);
            *(float4*)(out + rowbase + nb) = v;
        }
    }
}

// ---------------------------------------------------------------------------
extern "C" void kernel_launch(void* const* d_in, const int* in_sizes, int n_in,
                              void* d_out, int out_size) {
    const float* xyz = (const float*)d_in[0];
    const float* h   = (const float*)d_in[1];
    const float* x   = (const float*)d_in[2];
    const int*   knn = (const int*)  d_in[3];
    const float* wzp = (const float*)d_in[4];
    const float* bzp = (const float*)d_in[5];
    const float* wzo = (const float*)d_in[6];
    const float* bzo = (const float*)d_in[7];
    const float* wrp = (const float*)d_in[8];
    const float* brp = (const float*)d_in[9];
    const float* wro = (const float*)d_in[10];
    const float* bro = (const float*)d_in[11];
    const float* wqp = (const float*)d_in[12];
    const float* bqp = (const float*)d_in[13];
    const float* wqo = (const float*)d_in[14];
    const float* bqo = (const float*)d_in[15];
    float* out = (float*)d_out;

    k_wT<<<24, 256>>>(wzo, wro, wqo, wzp, bzp, wrp, brp, wqp, bqp);
    k_tr<<<(B_ * N_) / 64, 256>>>(h, x);
    k_zr<<<(B_ * N_) / NPB, 256>>>(xyz, knn, bzo, bro);
    k_q <<<(B_ * N_) / NPB, 256>>>(xyz, knn, bqo, h, out);
}

// round 14
// speedup vs baseline: 1.2436x; 1.0384x over previous
#include <cuda_runtime.h>
#include <cuda_fp16.h>
#include <cstdint>
#include <math.h>

#define B_    2
#define N_    65536
#define HID_  64
#define C_    128
#define NPB   32      // points per block (k_zr / k_q)
#define AP    132     // aggT row pad in floats

typedef unsigned int u32;

// Scratch (static device globals)
__device__ __half g_hx[(size_t)B_ * N_ * C_];    // [b][n][c] c<64: h, c>=64: x (fp16)
__device__ __half g_rh[(size_t)B_ * N_ * HID_];  // [b][n][o] r*h (fp16)
__device__ float  g_z [(size_t)B_ * HID_ * N_];  // [b][o][n] sigmoid(z)  (TRANSPOSED)
__device__ float4 g_wF[3 * 4 * 16 * 32];         // [gate][mt][kt][lane] A-fragments (tf32)
__device__ float4 g_wp4[3 * C_];                 // [g][c] = (w0,w1,w2,bias)

__device__ __forceinline__ float tanh_hw(float v) {
    float r; asm("tanh.approx.f32 %0, %1;" : "=f"(r) : "f"(v)); return r;
}
// sigmoid via HW tanh: 1 MUFU + FMA (vs EX2+RCP+mul+add)
__device__ __forceinline__ float sigm(float v) {
    return fmaf(0.5f, tanh_hw(0.5f * v), 0.5f);
}

__device__ __forceinline__ float tf32r(float v) {
    u32 r; asm("cvt.rna.tf32.f32 %0, %1;" : "=r"(r) : "f"(v));
    return __uint_as_float(r);
}

__device__ __forceinline__ void mma_tf32(float4& d, u32 a0, u32 a1, u32 a2, u32 a3,
                                         u32 b0, u32 b1) {
    asm volatile(
        "mma.sync.aligned.m16n8k8.row.col.f32.tf32.tf32.f32 "
        "{%0,%1,%2,%3}, {%4,%5,%6,%7}, {%8,%9}, {%0,%1,%2,%3};"
        : "+f"(d.x), "+f"(d.y), "+f"(d.z), "+f"(d.w)
        : "r"(a0), "r"(a1), "r"(a2), "r"(a3), "r"(b0), "r"(b1));
}

// ---------------------------------------------------------------------------
// Transpose: g_hx[b][n][c] = fp16(c<64 ? h[b][c][n] : x[b][c-64][n])  64-pt tiles
// First 24 blocks also prepare weights (folded k_wT).
// ---------------------------------------------------------------------------
__global__ __launch_bounds__(256) void k_tr(
    const float* __restrict__ h, const float* __restrict__ x,
    const float* __restrict__ wz, const float* __restrict__ wr,
    const float* __restrict__ wq,
    const float* __restrict__ wzp, const float* __restrict__ bzp,
    const float* __restrict__ wrp, const float* __restrict__ brp,
    const float* __restrict__ wqp, const float* __restrict__ bqp) {
    __shared__ float t[C_][66];
    const int b  = blockIdx.x >> 10;
    const int n0 = (blockIdx.x & 1023) * 64;
    const int tid  = threadIdx.x;
    const int lane = tid & 31;
    const int w    = tid >> 5;

    // Folded weight prep (blocks 0..23 cover 6144 fragment entries)
    if (blockIdx.x < 24) {
        int i = blockIdx.x * 256 + tid;
        {
            int gate = i >> 11;
            int r    = i & 2047;
            int mt   = r >> 9;
            int r2   = r & 511;
            int kt   = r2 >> 5;
            int ln   = r2 & 31;
            int g = ln >> 2, tt = ln & 3;
            int o = 16 * mt + g, c = 8 * kt + tt;
            const float* ww = (gate == 0) ? wz : ((gate == 1) ? wr : wq);
            float4 f;
            f.x = tf32r(ww[o * C_ + c]);
            f.y = tf32r(ww[(o + 8) * C_ + c]);
            f.z = tf32r(ww[o * C_ + c + 4]);
            f.w = tf32r(ww[(o + 8) * C_ + c + 4]);
            g_wF[i] = f;
        }
        if (i < 3 * C_) {
            int g = i >> 7, c = i & 127;
            const float* wp = (g == 0) ? wzp : ((g == 1) ? wrp : wqp);
            const float* bp = (g == 0) ? bzp : ((g == 1) ? brp : bqp);
            g_wp4[i] = make_float4(wp[3 * c], wp[3 * c + 1], wp[3 * c + 2], bp[c]);
        }
    }

    for (int r = w; r < C_; r += 8) {
        const float* src = (r < HID_)
            ? (h + ((size_t)(b * HID_ + r)) * N_)
            : (x + ((size_t)(b * HID_ + (r - HID_))) * N_);
        t[r][lane]      = src[n0 + lane];
        t[r][lane + 32] = src[n0 + lane + 32];
    }
    __syncthreads();

    const int nn = tid >> 2;          // 64 points, 4 threads per point
    const int q0 = tid & 3;
    __half* dst = g_hx + ((size_t)(b * N_ + n0 + nn)) * C_;
#pragma unroll
    for (int k = 0; k < 8; k++) {
        int c = 4 * (q0 + 4 * k);
        __half2 lo = __floats2half2_rn(t[c][nn],     t[c + 1][nn]);
        __half2 hi = __floats2half2_rn(t[c + 2][nn], t[c + 3][nn]);
        uint2 pk = make_uint2(*(u32*)&lo, *(u32*)&hi);
        *(uint2*)(dst + c) = pk;
    }
}

// ---------------------------------------------------------------------------
// ZR kernel: 32 points/block, 256 threads. fp16 gathers; zsm/rsm alias aggT.
// ---------------------------------------------------------------------------
__global__ __launch_bounds__(256, 5) void k_zr(
    const float* __restrict__ xyz, const int* __restrict__ knn,
    const float* __restrict__ bzo, const float* __restrict__ bro) {
    __shared__ __align__(16) float sbuf[2 * NPB * AP];
    __shared__ float4 srel4[NPB][4];
    __shared__ int    sidx[NPB][4];

    float (*aggT)[NPB][AP] = (float(*)[NPB][AP])sbuf;
    float (*zsm)[65] = (float(*)[65])sbuf;               // alias (post-sync)
    float (*rsm)[65] = (float(*)[65])(sbuf + NPB * 65);

    const int b   = blockIdx.x >> 11;
    const int n0  = (blockIdx.x & 2047) * NPB;
    const int tid = threadIdx.x;
    const int lane = tid & 31;
    const int w    = tid >> 5;

    if (tid < NPB * 4) {
        int pt = tid >> 2, j = tid & 3;
        int n  = n0 + pt;
        int m  = knn[((size_t)b * N_ + n) * 4 + j];
        sidx[pt][j] = m;
        const float* xb = xyz + (size_t)b * 3 * N_;
        srel4[pt][j] = make_float4(xb[m] - xb[n],
                                   xb[N_ + m] - xb[N_ + n],
                                   xb[2 * N_ + m] - xb[2 * N_ + n], 0.f);
    }
    __syncthreads();

    // Phase 1: fp16 gather + shared moments -> both gates' depthwise agg
    {
        const int half = w & 1;
        const int ptb  = w >> 1;
        const int c0   = half * HID_ + 2 * lane;
        const float4 Wz0 = g_wp4[c0],      Wz1 = g_wp4[c0 + 1];
        const float4 Wr0 = g_wp4[C_ + c0], Wr1 = g_wp4[C_ + c0 + 1];
        const __half* hxb = g_hx + (size_t)b * N_ * C_ + c0;
#pragma unroll
        for (int u = 0; u < 8; u++) {
            const int pt = ptb + 4 * u;
            int m[4];
#pragma unroll
            for (int j = 0; j < 4; j++) m[j] = sidx[pt][j];
            float2 gv[4];
#pragma unroll
            for (int j = 0; j < 4; j++)
                gv[j] = __half22float2(*(const __half2*)(hxb + (size_t)m[j] * C_));

            float m0a = 0.f, m1a = 0.f, m2a = 0.f, m3a = 0.f;
            float m0b = 0.f, m1b = 0.f, m2b = 0.f, m3b = 0.f;
#pragma unroll
            for (int j = 0; j < 4; j++) {
                float4 R = srel4[pt][j];
                float ga = gv[j].x, gb = gv[j].y;
                m0a += ga; m1a = fmaf(R.x, ga, m1a);
                m2a = fmaf(R.y, ga, m2a); m3a = fmaf(R.z, ga, m3a);
                m0b += gb; m1b = fmaf(R.x, gb, m1b);
                m2b = fmaf(R.y, gb, m2b); m3b = fmaf(R.z, gb, m3b);
            }
            float az0 = fmaf(Wz0.x, m1a, fmaf(Wz0.y, m2a, fmaf(Wz0.z, m3a, Wz0.w * m0a)));
            float az1 = fmaf(Wz1.x, m1b, fmaf(Wz1.y, m2b, fmaf(Wz1.z, m3b, Wz1.w * m0b)));
            float ar0 = fmaf(Wr0.x, m1a, fmaf(Wr0.y, m2a, fmaf(Wr0.z, m3a, Wr0.w * m0a)));
            float ar1 = fmaf(Wr1.x, m1b, fmaf(Wr1.y, m2b, fmaf(Wr1.z, m3b, Wr1.w * m0b)));
            *(float2*)&aggT[0][pt][c0] = make_float2(tf32r(az0), tf32r(az1));
            *(float2*)&aggT[1][pt][c0] = make_float2(tf32r(ar0), tf32r(ar1));
        }
    }
    __syncthreads();

    // Phase 2: tf32 mma. warp = (gate g2, m-tile mt); 4 n-tiles x 16 k-tiles
    {
        const int g2 = w >> 2;
        const int mt = w & 3;
        const int g  = lane >> 2, t = lane & 3;
        const float4* wf = g_wF + ((size_t)(g2 * 4 + mt) * 16) * 32 + lane;

        float4 acc[4];
#pragma unroll
        for (int nt = 0; nt < 4; nt++) acc[nt] = make_float4(0.f, 0.f, 0.f, 0.f);

#pragma unroll 4
        for (int kt = 0; kt < 16; kt++) {
            float4 A = wf[kt * 32];
            u32 a0 = __float_as_uint(A.x), a1 = __float_as_uint(A.y);
            u32 a2 = __float_as_uint(A.z), a3 = __float_as_uint(A.w);
#pragma unroll
            for (int nt = 0; nt < 4; nt++) {
                u32 b0 = __float_as_uint(aggT[g2][8 * nt + g][8 * kt + t]);
                u32 b1 = __float_as_uint(aggT[g2][8 * nt + g][8 * kt + t + 4]);
                mma_tf32(acc[nt], a0, a1, a2, a3, b0, b1);
            }
        }
        __syncthreads();   // aggT dead; zsm/rsm may now overwrite it

        const float* bo = g2 ? bro : bzo;
        const float b0v = bo[16 * mt + g];
        const float b1v = bo[16 * mt + g + 8];
        float (*dst)[65] = g2 ? rsm : zsm;
#pragma unroll
        for (int nt = 0; nt < 4; nt++) {
            int pt = 8 * nt + 2 * t;
            int o  = 16 * mt + g;
            dst[pt][o]         = sigm(acc[nt].x + b0v);
            dst[pt + 1][o]     = sigm(acc[nt].y + b0v);
            dst[pt][o + 8]     = sigm(acc[nt].z + b1v);
            dst[pt + 1][o + 8] = sigm(acc[nt].w + b1v);
        }
    }
    __syncthreads();

    // Phase 3a: z -> g_z transposed [b][o][n], coalesced float4
    {
        const int o = tid >> 2;
        const int q = tid & 3;
#pragma unroll
        for (int rep = 0; rep < 2; rep++) {
            int nb = 8 * q + 4 * rep;
            float4 v = make_float4(zsm[nb][o], zsm[nb + 1][o],
                                   zsm[nb + 2][o], zsm[nb + 3][o]);
            *(float4*)(g_z + ((size_t)(b * HID_ + o)) * N_ + n0 + nb) = v;
        }
    }
    // Phase 3b: r*h -> g_rh fp16 (half2 per thread)
    for (int i = tid; i < NPB * 32; i += 256) {
        int pt = i >> 5, o2 = 2 * (i & 31);
        size_t nb = (size_t)(b * N_ + n0 + pt);
        float2 hv = __half22float2(*(const __half2*)(g_hx + nb * C_ + o2));
        __half2 rh = __floats2half2_rn(rsm[pt][o2] * hv.x, rsm[pt][o2 + 1] * hv.y);
        *(__half2*)(g_rh + nb * HID_ + o2) = rh;
    }
}

// ---------------------------------------------------------------------------
// Q kernel: 32 points/block, 256 threads. fp16 gathers; osm aliases aggT.
// GRU combine fused into output phase with fp32 h from the ORIGINAL input.
// ---------------------------------------------------------------------------
__global__ __launch_bounds__(256, 6) void k_q(
    const float* __restrict__ xyz, const int* __restrict__ knn,
    const float* __restrict__ bqo, const float* __restrict__ hin,
    float* __restrict__ out) {
    __shared__ __align__(16) float sbuf[NPB * AP];
    __shared__ float4 srel4[NPB][4];
    __shared__ int    sidx[NPB][4];

    float (*aggT)[AP] = (float(*)[AP])sbuf;
    float (*osm)[65]  = (float(*)[65])sbuf;   // alias (post-sync)

    const int b   = blockIdx.x >> 11;
    const int n0  = (blockIdx.x & 2047) * NPB;
    const int tid = threadIdx.x;
    const int lane = tid & 31;
    const int w    = tid >> 5;

    if (tid < NPB * 4) {
        int pt = tid >> 2, j = tid & 3;
        int n  = n0 + pt;
        int m  = knn[((size_t)b * N_ + n) * 4 + j];
        sidx[pt][j] = m;
        const float* xb = xyz + (size_t)b * 3 * N_;
        srel4[pt][j] = make_float4(xb[m] - xb[n],
                                   xb[N_ + m] - xb[N_ + n],
                                   xb[2 * N_ + m] - xb[2 * N_ + n], 0.f);
    }
    __syncthreads();

    // Phase 1: fp16 gather r*h (half 0) or x (half 1) + depthwise agg
    {
        const int half = w & 1;
        const int ptb  = w >> 1;
        const int c0   = half * HID_ + 2 * lane;
        const float4 W0 = g_wp4[2 * C_ + c0], W1 = g_wp4[2 * C_ + c0 + 1];
        const __half* gbase = half
            ? (g_hx + (size_t)b * N_ * C_ + HID_ + 2 * lane)
            : (g_rh + (size_t)b * N_ * HID_ + 2 * lane);
        const int stride = half ? C_ : HID_;
#pragma unroll
        for (int u = 0; u < 8; u++) {
            const int pt = ptb + 4 * u;
            int m[4];
#pragma unroll
            for (int j = 0; j < 4; j++) m[j] = sidx[pt][j];
            float2 gv[4];
#pragma unroll
            for (int j = 0; j < 4; j++)
                gv[j] = __half22float2(*(const __half2*)(gbase + (size_t)m[j] * stride));

            float m0a = 0.f, m1a = 0.f, m2a = 0.f, m3a = 0.f;
            float m0b = 0.f, m1b = 0.f, m2b = 0.f, m3b = 0.f;
#pragma unroll
            for (int j = 0; j < 4; j++) {
                float4 R = srel4[pt][j];
                float ga = gv[j].x, gb = gv[j].y;
                m0a += ga; m1a = fmaf(R.x, ga, m1a);
                m2a = fmaf(R.y, ga, m2a); m3a = fmaf(R.z, ga, m3a);
                m0b += gb; m1b = fmaf(R.x, gb, m1b);
                m2b = fmaf(R.y, gb, m2b); m3b = fmaf(R.z, gb, m3b);
            }
            float a0 = fmaf(W0.x, m1a, fmaf(W0.y, m2a, fmaf(W0.z, m3a, W0.w * m0a)));
            float a1 = fmaf(W1.x, m1b, fmaf(W1.y, m2b, fmaf(W1.z, m3b, W1.w * m0b)));
            *(float2*)&aggT[pt][c0] = make_float2(tf32r(a0), tf32r(a1));
        }
    }
    __syncthreads();

    // Phase 2: tf32 mma. warp = (m-tile mt, n-half nh); HW tanh -> osm (aliased)
    {
        const int mt = w & 3;
        const int nh = w >> 2;
        const int g  = lane >> 2, t = lane & 3;
        const float4* wf = g_wF + ((size_t)(2 * 4 + mt) * 16) * 32 + lane;

        float4 acc[2];
        acc[0] = make_float4(0.f, 0.f, 0.f, 0.f);
        acc[1] = make_float4(0.f, 0.f, 0.f, 0.f);

#pragma unroll 4
        for (int kt = 0; kt < 16; kt++) {
            float4 A = wf[kt * 32];
            u32 a0 = __float_as_uint(A.x), a1 = __float_as_uint(A.y);
            u32 a2 = __float_as_uint(A.z), a3 = __float_as_uint(A.w);
#pragma unroll
            for (int j = 0; j < 2; j++) {
                int nt = 2 * nh + j;
                u32 b0 = __float_as_uint(aggT[8 * nt + g][8 * kt + t]);
                u32 b1 = __float_as_uint(aggT[8 * nt + g][8 * kt + t + 4]);
                mma_tf32(acc[j], a0, a1, a2, a3, b0, b1);
            }
        }
        __syncthreads();   // aggT dead; osm may now overwrite it

        const float b0v = bqo[16 * mt + g];
        const float b1v = bqo[16 * mt + g + 8];
#pragma unroll
        for (int j = 0; j < 2; j++) {
            int pt = 8 * (2 * nh + j) + 2 * t;
            int o  = 16 * mt + g;
            osm[pt][o]         = tanh_hw(acc[j].x + b0v);
            osm[pt + 1][o]     = tanh_hw(acc[j].y + b0v);
            osm[pt][o + 8]     = tanh_hw(acc[j].z + b1v);
            osm[pt + 1][o + 8] = tanh_hw(acc[j].w + b1v);
        }
    }
    __syncthreads();

    // Phase 3: fused GRU combine + coalesced output. z/h/out all [b][o][n].
    {
        const int o = tid >> 2;
        const int q = tid & 3;
        size_t rowbase = ((size_t)(b * HID_ + o)) * N_ + n0;
#pragma unroll
        for (int rep = 0; rep < 2; rep++) {
            int nb = 8 * q + 4 * rep;
            float4 zv = *(const float4*)(g_z + rowbase + nb);
            float4 hv = *(const float4*)(hin + rowbase + nb);
            float4 v;
            v.x = fmaf(zv.x, osm[nb][o]     - hv.x, hv.x);
            v.y = fmaf(zv.y, osm[nb + 1][o] - hv.y, hv.y);
            v.z = fmaf(zv.z, osm[nb + 2][o] - hv.z, hv.z);
            v.w = fmaf(zv.w, osm[nb + 3][o] - hv.w, hv.w);
            *(float4*)(out + rowbase + nb) = v;
        }
    }
}

// ---------------------------------------------------------------------------
extern "C" void kernel_launch(void* const* d_in, const int* in_sizes, int n_in,
                              void* d_out, int out_size) {
    const float* xyz = (const float*)d_in[0];
    const float* h   = (const float*)d_in[1];
    const float* x   = (const float*)d_in[2];
    const int*   knn = (const int*)  d_in[3];
    const float* wzp = (const float*)d_in[4];
    const float* bzp = (const float*)d_in[5];
    const float* wzo = (const float*)d_in[6];
    const float* bzo = (const float*)d_in[7];
    const float* wrp = (const float*)d_in[8];
    const float* brp = (const float*)d_in[9];
    const float* wro = (const float*)d_in[10];
    const float* bro = (const float*)d_in[11];
    const float* wqp = (const float*)d_in[12];
    const float* bqp = (const float*)d_in[13];
    const float* wqo = (const float*)d_in[14];
    const float* bqo = (const float*)d_in[15];
    float* out = (float*)d_out;

    k_tr<<<(B_ * N_) / 64, 256>>>(h, x, wzo, wro, wqo,
                                  wzp, bzp, wrp, brp, wqp, bqp);
    k_zr<<<(B_ * N_) / NPB, 256>>>(xyz, knn, bzo, bro);
    k_q <<<(B_ * N_) / NPB, 256>>>(xyz, knn, bqo, h, out);
}

// round 17
// speedup vs baseline: 1.3321x; 1.0712x over previous
#include <cuda_runtime.h>
#include <cuda_fp16.h>
#include <cstdint>
#include <math.h>

#define B_    2
#define N_    65536
#define HID_  64
#define C_    128
#define NPB   32      // points per block (k_zr / k_q)
#define AP    132     // aggT row pad in floats

typedef unsigned int u32;

// Scratch (static device globals)
__device__ __half g_hx[(size_t)B_ * N_ * C_];    // [b][n][c] c<64: h, c>=64: x (fp16)
__device__ __half g_rh[(size_t)B_ * N_ * HID_];  // [b][n][o] r*h (fp16)
__device__ float  g_z [(size_t)B_ * HID_ * N_];  // [b][o][n] sigmoid(z)  (TRANSPOSED)
__device__ float4 g_wF[3 * 4 * 16 * 32];         // [gate][mt][kt][lane] A-fragments (tf32)
__device__ float4 g_wp4[3 * C_];                 // [g][c] = (w0,w1,w2,bias)

__device__ __forceinline__ float tanh_hw(float v) {
    float r; asm("tanh.approx.f32 %0, %1;" : "=f"(r) : "f"(v)); return r;
}
// sigmoid via HW tanh: 1 MUFU + FMA
__device__ __forceinline__ float sigm(float v) {
    return fmaf(0.5f, tanh_hw(0.5f * v), 0.5f);
}

__device__ __forceinline__ float tf32r(float v) {
    u32 r; asm("cvt.rna.tf32.f32 %0, %1;" : "=r"(r) : "f"(v));
    return __uint_as_float(r);
}

__device__ __forceinline__ void mma_tf32(float4& d, u32 a0, u32 a1, u32 a2, u32 a3,
                                         u32 b0, u32 b1) {
    asm volatile(
        "mma.sync.aligned.m16n8k8.row.col.f32.tf32.tf32.f32 "
        "{%0,%1,%2,%3}, {%4,%5,%6,%7}, {%8,%9}, {%0,%1,%2,%3};"
        : "+f"(d.x), "+f"(d.y), "+f"(d.z), "+f"(d.w)
        : "r"(a0), "r"(a1), "r"(a2), "r"(a3), "r"(b0), "r"(b1));
}

// ---------------------------------------------------------------------------
// Transpose: g_hx[b][n][c] = fp16(c<64 ? h[b][c][n] : x[b][c-64][n])  64-pt tiles
// Wide float4 loads (8-deep MLP). First 24 blocks also prepare weights.
// ---------------------------------------------------------------------------
__global__ __launch_bounds__(256) void k_tr(
    const float* __restrict__ h, const float* __restrict__ x,
    const float* __restrict__ wz, const float* __restrict__ wr,
    const float* __restrict__ wq,
    const float* __restrict__ wzp, const float* __restrict__ bzp,
    const float* __restrict__ wrp, const float* __restrict__ brp,
    const float* __restrict__ wqp, const float* __restrict__ bqp) {
    __shared__ float t[C_][66];
    const int b  = blockIdx.x >> 10;
    const int n0 = (blockIdx.x & 1023) * 64;
    const int tid  = threadIdx.x;

    // Folded weight prep (blocks 0..23 cover 6144 fragment entries)
    if (blockIdx.x < 24) {
        int i = blockIdx.x * 256 + tid;
        {
            int gate = i >> 11;
            int r    = i & 2047;
            int mt   = r >> 9;
            int r2   = r & 511;
            int kt   = r2 >> 5;
            int ln   = r2 & 31;
            int g = ln >> 2, tt = ln & 3;
            int o = 16 * mt + g, c = 8 * kt + tt;
            const float* ww = (gate == 0) ? wz : ((gate == 1) ? wr : wq);
            float4 f;
            f.x = tf32r(ww[o * C_ + c]);
            f.y = tf32r(ww[(o + 8) * C_ + c]);
            f.z = tf32r(ww[o * C_ + c + 4]);
            f.w = tf32r(ww[(o + 8) * C_ + c + 4]);
            g_wF[i] = f;
        }
        if (i < 3 * C_) {
            int g = i >> 7, c = i & 127;
            const float* wp = (g == 0) ? wzp : ((g == 1) ? wrp : wqp);
            const float* bp = (g == 0) ? bzp : ((g == 1) ? brp : bqp);
            g_wp4[i] = make_float4(wp[3 * c], wp[3 * c + 1], wp[3 * c + 2], bp[c]);
        }
    }

    // Load phase: thread handles one float4 per pass, 8 passes (8-deep MLP)
    {
        const int rr = tid >> 4;          // 0..15
        const int c4 = (tid & 15) * 4;    // 0..60
#pragma unroll
        for (int p = 0; p < 8; p++) {
            int r = 16 * p + rr;
            const float* src = (r < HID_)
                ? (h + ((size_t)(b * HID_ + r)) * N_)
                : (x + ((size_t)(b * HID_ + (r - HID_))) * N_);
            float4 v = *(const float4*)(src + n0 + c4);
            *(float2*)&t[r][c4]     = make_float2(v.x, v.y);
            *(float2*)&t[r][c4 + 2] = make_float2(v.z, v.w);
        }
    }
    __syncthreads();

    const int nn = tid >> 2;          // 64 points, 4 threads per point
    const int q0 = tid & 3;
    __half* dst = g_hx + ((size_t)(b * N_ + n0 + nn)) * C_;
#pragma unroll
    for (int k = 0; k < 8; k++) {
        int c = 4 * (q0 + 4 * k);
        __half2 lo = __floats2half2_rn(t[c][nn],     t[c + 1][nn]);
        __half2 hi = __floats2half2_rn(t[c + 2][nn], t[c + 3][nn]);
        uint2 pk = make_uint2(*(u32*)&lo, *(u32*)&hi);
        *(uint2*)(dst + c) = pk;
    }
}

// ---------------------------------------------------------------------------
// ZR kernel: 32 points/block, 256 threads. fp16 gathers; zsm/rsm alias aggT.
// ---------------------------------------------------------------------------
__global__ __launch_bounds__(256, 5) void k_zr(
    const float* __restrict__ xyz, const int* __restrict__ knn,
    const float* __restrict__ bzo, const float* __restrict__ bro) {
    __shared__ __align__(16) float sbuf[2 * NPB * AP];
    __shared__ float4 srel4[NPB][4];
    __shared__ int    sidx[NPB][4];

    float (*aggT)[NPB][AP] = (float(*)[NPB][AP])sbuf;
    float (*zsm)[65] = (float(*)[65])sbuf;               // alias (post-sync)
    float (*rsm)[65] = (float(*)[65])(sbuf + NPB * 65);

    const int b   = blockIdx.x >> 11;
    const int n0  = (blockIdx.x & 2047) * NPB;
    const int tid = threadIdx.x;
    const int lane = tid & 31;
    const int w    = tid >> 5;

    if (tid < NPB * 4) {
        int pt = tid >> 2, j = tid & 3;
        int n  = n0 + pt;
        int m  = knn[((size_t)b * N_ + n) * 4 + j];
        sidx[pt][j] = m;
        const float* xb = xyz + (size_t)b * 3 * N_;
        srel4[pt][j] = make_float4(xb[m] - xb[n],
                                   xb[N_ + m] - xb[N_ + n],
                                   xb[2 * N_ + m] - xb[2 * N_ + n], 0.f);
    }
    __syncthreads();

    // Phase 1: fp16 gather + shared moments -> both gates' depthwise agg
    {
        const int half = w & 1;
        const int ptb  = w >> 1;
        const int c0   = half * HID_ + 2 * lane;
        const float4 Wz0 = g_wp4[c0],      Wz1 = g_wp4[c0 + 1];
        const float4 Wr0 = g_wp4[C_ + c0], Wr1 = g_wp4[C_ + c0 + 1];
        const __half* hxb = g_hx + (size_t)b * N_ * C_ + c0;
#pragma unroll
        for (int u = 0; u < 8; u++) {
            const int pt = ptb + 4 * u;
            int m[4];
#pragma unroll
            for (int j = 0; j < 4; j++) m[j] = sidx[pt][j];
            float2 gv[4];
#pragma unroll
            for (int j = 0; j < 4; j++)
                gv[j] = __half22float2(*(const __half2*)(hxb + (size_t)m[j] * C_));

            float m0a = 0.f, m1a = 0.f, m2a = 0.f, m3a = 0.f;
            float m0b = 0.f, m1b = 0.f, m2b = 0.f, m3b = 0.f;
#pragma unroll
            for (int j = 0; j < 4; j++) {
                float4 R = srel4[pt][j];
                float ga = gv[j].x, gb = gv[j].y;
                m0a += ga; m1a = fmaf(R.x, ga, m1a);
                m2a = fmaf(R.y, ga, m2a); m3a = fmaf(R.z, ga, m3a);
                m0b += gb; m1b = fmaf(R.x, gb, m1b);
                m2b = fmaf(R.y, gb, m2b); m3b = fmaf(R.z, gb, m3b);
            }
            float az0 = fmaf(Wz0.x, m1a, fmaf(Wz0.y, m2a, fmaf(Wz0.z, m3a, Wz0.w * m0a)));
            float az1 = fmaf(Wz1.x, m1b, fmaf(Wz1.y, m2b, fmaf(Wz1.z, m3b, Wz1.w * m0b)));
            float ar0 = fmaf(Wr0.x, m1a, fmaf(Wr0.y, m2a, fmaf(Wr0.z, m3a, Wr0.w * m0a)));
            float ar1 = fmaf(Wr1.x, m1b, fmaf(Wr1.y, m2b, fmaf(Wr1.z, m3b, Wr1.w * m0b)));
            *(float2*)&aggT[0][pt][c0] = make_float2(tf32r(az0), tf32r(az1));
            *(float2*)&aggT[1][pt][c0] = make_float2(tf32r(ar0), tf32r(ar1));
        }
    }
    __syncthreads();

    // Phase 2: tf32 mma. warp = (gate g2, m-tile mt); 4 n-tiles x 16 k-tiles
    {
        const int g2 = w >> 2;
        const int mt = w & 3;
        const int g  = lane >> 2, t = lane & 3;
        const float4* wf = g_wF + ((size_t)(g2 * 4 + mt) * 16) * 32 + lane;

        float4 acc[4];
#pragma unroll
        for (int nt = 0; nt < 4; nt++) acc[nt] = make_float4(0.f, 0.f, 0.f, 0.f);

#pragma unroll 4
        for (int kt = 0; kt < 16; kt++) {
            float4 A = wf[kt * 32];
            u32 a0 = __float_as_uint(A.x), a1 = __float_as_uint(A.y);
            u32 a2 = __float_as_uint(A.z), a3 = __float_as_uint(A.w);
#pragma unroll
            for (int nt = 0; nt < 4; nt++) {
                u32 b0 = __float_as_uint(aggT[g2][8 * nt + g][8 * kt + t]);
                u32 b1 = __float_as_uint(aggT[g2][8 * nt + g][8 * kt + t + 4]);
                mma_tf32(acc[nt], a0, a1, a2, a3, b0, b1);
            }
        }
        __syncthreads();   // aggT dead; zsm/rsm may now overwrite it

        const float* bo = g2 ? bro : bzo;
        const float b0v = bo[16 * mt + g];
        const float b1v = bo[16 * mt + g + 8];
        float (*dst)[65] = g2 ? rsm : zsm;
#pragma unroll
        for (int nt = 0; nt < 4; nt++) {
            int pt = 8 * nt + 2 * t;
            int o  = 16 * mt + g;
            dst[pt][o]         = sigm(acc[nt].x + b0v);
            dst[pt + 1][o]     = sigm(acc[nt].y + b0v);
            dst[pt][o + 8]     = sigm(acc[nt].z + b1v);
            dst[pt + 1][o + 8] = sigm(acc[nt].w + b1v);
        }
    }
    __syncthreads();

    // Phase 3a: z -> g_z transposed [b][o][n], coalesced float4
    {
        const int o = tid >> 2;
        const int q = tid & 3;
#pragma unroll
        for (int rep = 0; rep < 2; rep++) {
            int nb = 8 * q + 4 * rep;
            float4 v = make_float4(zsm[nb][o], zsm[nb + 1][o],
                                   zsm[nb + 2][o], zsm[nb + 3][o]);
            *(float4*)(g_z + ((size_t)(b * HID_ + o)) * N_ + n0 + nb) = v;
        }
    }
    // Phase 3b: r*h -> g_rh fp16 (half2 per thread)
    for (int i = tid; i < NPB * 32; i += 256) {
        int pt = i >> 5, o2 = 2 * (i & 31);
        size_t nb = (size_t)(b * N_ + n0 + pt);
        float2 hv = __half22float2(*(const __half2*)(g_hx + nb * C_ + o2));
        __half2 rh = __floats2half2_rn(rsm[pt][o2] * hv.x, rsm[pt][o2 + 1] * hv.y);
        *(__half2*)(g_rh + nb * HID_ + o2) = rh;
    }
}

// ---------------------------------------------------------------------------
// Q kernel: 32 points/block, 256 threads. fp16 gathers; osm aliases aggT.
// GRU combine fused into output phase with fp32 h from the ORIGINAL input.
// ---------------------------------------------------------------------------
__global__ __launch_bounds__(256, 6) void k_q(
    const float* __restrict__ xyz, const int* __restrict__ knn,
    const float* __restrict__ bqo, const float* __restrict__ hin,
    float* __restrict__ out) {
    __shared__ __align__(16) float sbuf[NPB * AP];
    __shared__ float4 srel4[NPB][4];
    __shared__ int    sidx[NPB][4];

    float (*aggT)[AP] = (float(*)[AP])sbuf;
    float (*osm)[65]  = (float(*)[65])sbuf;   // alias (post-sync)

    const int b   = blockIdx.x >> 11;
    const int n0  = (blockIdx.x & 2047) * NPB;
    const int tid = threadIdx.x;
    const int lane = tid & 31;
    const int w    = tid >> 5;

    if (tid < NPB * 4) {
        int pt = tid >> 2, j = tid & 3;
        int n  = n0 + pt;
        int m  = knn[((size_t)b * N_ + n) * 4 + j];
        sidx[pt][j] = m;
        const float* xb = xyz + (size_t)b * 3 * N_;
        srel4[pt][j] = make_float4(xb[m] - xb[n],
                                   xb[N_ + m] - xb[N_ + n],
                                   xb[2 * N_ + m] - xb[2 * N_ + n], 0.f);
    }
    __syncthreads();

    // Phase 1: fp16 gather r*h (half 0) or x (half 1) + depthwise agg
    {
        const int half = w & 1;
        const int ptb  = w >> 1;
        const int c0   = half * HID_ + 2 * lane;
        const float4 W0 = g_wp4[2 * C_ + c0], W1 = g_wp4[2 * C_ + c0 + 1];
        const __half* gbase = half
            ? (g_hx + (size_t)b * N_ * C_ + HID_ + 2 * lane)
            : (g_rh + (size_t)b * N_ * HID_ + 2 * lane);
        const int stride = half ? C_ : HID_;
#pragma unroll
        for (int u = 0; u < 8; u++) {
            const int pt = ptb + 4 * u;
            int m[4];
#pragma unroll
            for (int j = 0; j < 4; j++) m[j] = sidx[pt][j];
            float2 gv[4];
#pragma unroll
            for (int j = 0; j < 4; j++)
                gv[j] = __half22float2(*(const __half2*)(gbase + (size_t)m[j] * stride));

            float m0a = 0.f, m1a = 0.f, m2a = 0.f, m3a = 0.f;
            float m0b = 0.f, m1b = 0.f, m2b = 0.f, m3b = 0.f;
#pragma unroll
            for (int j = 0; j < 4; j++) {
                float4 R = srel4[pt][j];
                float ga = gv[j].x, gb = gv[j].y;
                m0a += ga; m1a = fmaf(R.x, ga, m1a);
                m2a = fmaf(R.y, ga, m2a); m3a = fmaf(R.z, ga, m3a);
                m0b += gb; m1b = fmaf(R.x, gb, m1b);
                m2b = fmaf(R.y, gb, m2b); m3b = fmaf(R.z, gb, m3b);
            }
            float a0 = fmaf(W0.x, m1a, fmaf(W0.y, m2a, fmaf(W0.z, m3a, W0.w * m0a)));
            float a1 = fmaf(W1.x, m1b, fmaf(W1.y, m2b, fmaf(W1.z, m3b, W1.w * m0b)));
            *(float2*)&aggT[pt][c0] = make_float2(tf32r(a0), tf32r(a1));
        }
    }
    __syncthreads();

    // Phase 2: tf32 mma. warp = (m-tile mt, n-half nh); HW tanh -> osm (aliased)
    {
        const int mt = w & 3;
        const int nh = w >> 2;
        const int g  = lane >> 2, t = lane & 3;
        const float4* wf = g_wF + ((size_t)(2 * 4 + mt) * 16) * 32 + lane;

        float4 acc[2];
        acc[0] = make_float4(0.f, 0.f, 0.f, 0.f);
        acc[1] = make_float4(0.f, 0.f, 0.f, 0.f);

#pragma unroll 4
        for (int kt = 0; kt < 16; kt++) {
            float4 A = wf[kt * 32];
            u32 a0 = __float_as_uint(A.x), a1 = __float_as_uint(A.y);
            u32 a2 = __float_as_uint(A.z), a3 = __float_as_uint(A.w);
#pragma unroll
            for (int j = 0; j < 2; j++) {
                int nt = 2 * nh + j;
                u32 b0 = __float_as_uint(aggT[8 * nt + g][8 * kt + t]);
                u32 b1 = __float_as_uint(aggT[8 * nt + g][8 * kt + t + 4]);
                mma_tf32(acc[j], a0, a1, a2, a3, b0, b1);
            }
        }
        __syncthreads();   // aggT dead; osm may now overwrite it

        const float b0v = bqo[16 * mt + g];
        const float b1v = bqo[16 * mt + g + 8];
#pragma unroll
        for (int j = 0; j < 2; j++) {
            int pt = 8 * (2 * nh + j) + 2 * t;
            int o  = 16 * mt + g;
            osm[pt][o]         = tanh_hw(acc[j].x + b0v);
            osm[pt + 1][o]     = tanh_hw(acc[j].y + b0v);
            osm[pt][o + 8]     = tanh_hw(acc[j].z + b1v);
            osm[pt + 1][o + 8] = tanh_hw(acc[j].w + b1v);
        }
    }
    __syncthreads();

    // Phase 3: fused GRU combine + coalesced output. z/h/out all [b][o][n].
    {
        const int o = tid >> 2;
        const int q = tid & 3;
        size_t rowbase = ((size_t)(b * HID_ + o)) * N_ + n0;
#pragma unroll
        for (int rep = 0; rep < 2; rep++) {
            int nb = 8 * q + 4 * rep;
            float4 zv = *(const float4*)(g_z + rowbase + nb);
            float4 hv = *(const float4*)(hin + rowbase + nb);
            float4 v;
            v.x = fmaf(zv.x, osm[nb][o]     - hv.x, hv.x);
            v.y = fmaf(zv.y, osm[nb + 1][o] - hv.y, hv.y);
            v.z = fmaf(zv.z, osm[nb + 2][o] - hv.z, hv.z);
            v.w = fmaf(zv.w, osm[nb + 3][o] - hv.w, hv.w);
            *(float4*)(out + rowbase + nb) = v;
        }
    }
}

// ---------------------------------------------------------------------------
extern "C" void kernel_launch(void* const* d_in, const int* in_sizes, int n_in,
                              void* d_out, int out_size) {
    const float* xyz = (const float*)d_in[0];
    const float* h   = (const float*)d_in[1];
    const float* x   = (const float*)d_in[2];
    const int*   knn = (const int*)  d_in[3];
    const float* wzp = (const float*)d_in[4];
    const float* bzp = (const float*)d_in[5];
    const float* wzo = (const float*)d_in[6];
    const float* bzo = (const float*)d_in[7];
    const float* wrp = (const float*)d_in[8];
    const float* brp = (const float*)d_in[9];
    const float* wro = (const float*)d_in[10];
    const float* bro = (const float*)d_in[11];
    const float* wqp = (const float*)d_in[12];
    const float* bqp = (const float*)d_in[13];
    const float* wqo = (const float*)d_in[14];
    const float* bqo = (const float*)d_in[15];
    float* out = (float*)d_out;

    k_tr<<<(B_ * N_) / 64, 256>>>(h, x, wzo, wro, wqo,
                                  wzp, bzp, wrp, brp, wqp, bqp);
    k_zr<<<(B_ * N_) / NPB, 256>>>(xyz, knn, bzo, bro);
    k_q <<<(B_ * N_) / NPB, 256>>>(xyz, knn, bqo, h, out);
}